// round 17
// baseline (speedup 1.0000x reference)
#include <cuda_runtime.h>
#include <stdint.h>

#define BATCH  4
#define NPTS   64
#define DIM    128
#define NFULL  (NPTS*NPTS)     // 4096
#define NPRED  2016            // classes (i<j)
#define NPREPC 128             // prep units (b, t, s16)
#define NLOSSU 1008            // loss units (b, ph, c126)
#define GRID_F 888             // fused grid (>= resident capacity not required for
                               // correctness; prep bids 0..127 are wave-1 resident)

__device__ float g_C [(size_t)BATCH*2*NPRED*64];        // [b][t][k][p] scaled diff rows
// packed masked table: [b][p*32+m] = (rns[p][m], rns[p][m+32], -rnt[p][m], -rnt[p][m+32])
__device__ __align__(16) float4 g_rnTab4[BATCH][64*32];
__device__ double g_acc;
__device__ unsigned int g_done;
__device__ unsigned int g_ready;

struct SMPrep {
    float sXT[32][67];
    float G[64 * 64];
    float sRNl[126];
    int   sI[126], sJ[126];
};
struct SMLoss {
    float4 sTab[32 * 32];
    float4 sCp[8][32];
    float  wsum[8];
};
union SMU { SMPrep p; SMLoss l; };

// ---------------------------------------------------------------- fused kernel
__global__ __launch_bounds__(256) void fused_k(const float* __restrict__ student,
                                               const float* __restrict__ teacher,
                                               float* __restrict__ out) {
    __shared__ __align__(16) SMU sm;
    int tid = threadIdx.x, wid = tid >> 5, lane = tid & 31;
    int bid = blockIdx.x;

    // ================= PHASE 1: prep (bids 0..127) =================
    if (bid < NPREPC) {
        int b = bid >> 5, t = (bid >> 4) & 1, s = bid & 15;
        const float* X = (t ? teacher : student) + (size_t)b * NPTS * DIM;

        // zero invalid table slots (disjoint from all valid writes)
        if (t == 0 && s == 0) {
            for (int u = tid; u < 64 * 32; u += 256) {
                int p = u >> 5, m = u & 31;
                float* e = (float*)&g_rnTab4[b][u];
                if (m <= p || p == 63)      { e[0] = 0.f; e[2] = 0.f; }
                if (m + 32 <= p || p == 63) { e[1] = 0.f; e[3] = 0.f; }
            }
        }

        int bi = tid >> 4, bj = tid & 15;
        float acc[4][4];
        #pragma unroll
        for (int r = 0; r < 4; r++)
            #pragma unroll
            for (int c = 0; c < 4; c++) acc[r][c] = 0.f;

        for (int dq = 0; dq < 4; dq++) {
            if (dq) __syncthreads();
            for (int u = tid; u < NPTS * 32; u += 256) {
                int n = u >> 5, d = u & 31;
                sm.p.sXT[d][n] = X[(size_t)n * DIM + dq * 32 + d];
            }
            __syncthreads();
            #pragma unroll 4
            for (int d = 0; d < 32; d++) {
                float xi[4], xj[4];
                #pragma unroll
                for (int r = 0; r < 4; r++) xi[r] = sm.p.sXT[d][bi * 4 + r];
                #pragma unroll
                for (int c = 0; c < 4; c++) xj[c] = sm.p.sXT[d][bj * 4 + c];
                #pragma unroll
                for (int r = 0; r < 4; r++)
                    #pragma unroll
                    for (int c = 0; c < 4; c++) acc[r][c] += xi[r] * xj[c];
            }
        }
        #pragma unroll
        for (int r = 0; r < 4; r++)
            #pragma unroll
            for (int c = 0; c < 4; c++)
                sm.p.G[(bi * 4 + r) * 64 + (bj * 4 + c)] = acc[r][c];
        __syncthreads();

        if (tid < 126) {
            int l = s * 126 + tid;
            int p = 0, rem = l;
            while (rem >= 63 - p) { rem -= 63 - p; p++; }
            int q = p + 1 + rem;
            float ss = sm.p.G[p * 64 + p] - 2.f * sm.p.G[p * 64 + q] + sm.p.G[q * 64 + q];
            float rn = 1.f / fmaxf(sqrtf(fmaxf(ss, 0.f)), 1e-12f);
            sm.p.sI[tid] = p; sm.p.sJ[tid] = q; sm.p.sRNl[tid] = rn;
            ((float*)&g_rnTab4[b][p * 32 + (q & 31)])[(q >> 5) + 2 * t] = t ? -rn : rn;
        }
        __syncthreads();

        for (int u = tid; u < 126 * 64; u += 256) {
            int kl = u >> 6, p = u & 63;
            float val = (sm.p.G[sm.p.sI[kl] * 64 + p] - sm.p.G[sm.p.sJ[kl] * 64 + p])
                        * sm.p.sRNl[kl];
            g_C[((size_t)(b * 2 + t) * NPRED + s * 126 + kl) * 64 + p] = val;
        }

        // publish: all threads' writes fenced, then one flag increment
        __threadfence();
        __syncthreads();
        if (tid == 0) atomicAdd(&g_ready, 1u);
    }

    // ================= barrier: wait for all prep CTAs =================
    if (tid == 0) {
        while (*((volatile unsigned int*)&g_ready) < NPREPC) { }
    }
    __syncthreads();
    __threadfence();

    // ================= PHASE 2: loss units =================
    float acc0 = 0.f, acc1 = 0.f, acc2 = 0.f, acc3 = 0.f;
    for (int u = bid; u < NLOSSU; u += GRID_F) {
        __syncthreads();                       // smem reuse across units/phases
        int b = u / 252;
        int r = u - b * 252;
        int ph = r / 126;
        int c = r - ph * 126;

        {
            const float4* src = g_rnTab4[b] + ph * 32 * 32;
            #pragma unroll
            for (int v = 0; v < 4; v++) sm.l.sTab[tid + v * 256] = src[tid + v * 256];
        }

        int k0 = c * 16 + wid;
        int k1 = c * 16 + 8 + wid;
        const float* Cs0 = g_C + ((size_t)(b * 2 + 0) * NPRED + k0) * 64;
        const float* Ct0 = g_C + ((size_t)(b * 2 + 1) * NPRED + k0) * 64;
        const float* Cs1 = g_C + ((size_t)(b * 2 + 0) * NPRED + k1) * 64;
        const float* Ct1 = g_C + ((size_t)(b * 2 + 1) * NPRED + k1) * 64;
        float s0a = Cs0[lane], s0b = Cs0[lane + 32];
        float t0a = Ct0[lane], t0b = Ct0[lane + 32];
        float s1a = Cs1[lane], s1b = Cs1[lane + 32];
        float t1a = Ct1[lane], t1b = Ct1[lane + 32];

        sm.l.sCp[wid][lane] = ph ? make_float4(s0b, t0b, s1b, t1b)
                                 : make_float4(s0a, t0a, s1a, t1a);
        __syncthreads();

        #pragma unroll
        for (int pp = 0; pp < 32; pp++) {
            float4 rl = sm.l.sTab[pp * 32 + lane];
            float4 cp = sm.l.sCp[wid][pp];     // uniform address -> broadcast
            {
                float d = (cp.x - s0a) * rl.x + (cp.y - t0a) * rl.z;
                float a = fabsf(d), m = fminf(a, 1.f);
                acc0 += m * (a - 0.5f * m);
            }
            {
                float d = (cp.x - s0b) * rl.y + (cp.y - t0b) * rl.w;
                float a = fabsf(d), m = fminf(a, 1.f);
                acc1 += m * (a - 0.5f * m);
            }
            {
                float d = (cp.z - s1a) * rl.x + (cp.w - t1a) * rl.z;
                float a = fabsf(d), m = fminf(a, 1.f);
                acc2 += m * (a - 0.5f * m);
            }
            {
                float d = (cp.z - s1b) * rl.y + (cp.w - t1b) * rl.w;
                float a = fabsf(d), m = fminf(a, 1.f);
                acc3 += m * (a - 0.5f * m);
            }
        }
    }

    // ================= reduce + finalize + reset =================
    float lsum = (acc0 + acc1) + (acc2 + acc3);
    #pragma unroll
    for (int o = 16; o; o >>= 1) lsum += __shfl_xor_sync(0xffffffffu, lsum, o);
    __syncthreads();
    if (lane == 0) sm.l.wsum[wid] = lsum;
    __syncthreads();
    if (tid == 0) {
        float sblk = 0.f;
        #pragma unroll
        for (int w2 = 0; w2 < 8; w2++) sblk += sm.l.wsum[w2];
        atomicAdd(&g_acc, (double)sblk);
        __threadfence();
        unsigned int ticket = atomicAdd(&g_done, 1u);
        if (ticket == GRID_F - 1) {
            double v = *((volatile double*)&g_acc);
            out[0] = (float)(4.0 * v / ((double)BATCH * NFULL * NFULL));
            __threadfence();
            // reset state for the next graph replay (deterministic re-run)
            g_acc = 0.0;
            g_ready = 0u;
            g_done = 0u;
        }
    }
}

extern "C" void kernel_launch(void* const* d_in, const int* in_sizes, int n_in,
                              void* d_out, int out_size) {
    const float* student = (const float*)d_in[0];
    const float* teacher = (const float*)d_in[1];
    fused_k<<<GRID_F, 256>>>(student, teacher, (float*)d_out);
}